// round 7
// baseline (speedup 1.0000x reference)
#include <cuda_runtime.h>
#include <cstdint>

#define BATCH 2
#define SEQ   2048
#define NHEAD 16
#define HDIM  64
#define EDIM  1024

// Scratch (static device globals: allocation-free per harness rules)
__device__ float g_q[(size_t)BATCH * NHEAD * SEQ * HDIM];     // tf32
__device__ float g_k[(size_t)BATCH * NHEAD * SEQ * HDIM];     // tf32
__device__ float g_v[(size_t)BATCH * NHEAD * SEQ * HDIM];     // tf32, TRANSPOSED [b,h,d,s]
__device__ float g_att[(size_t)BATCH * SEQ * EDIM];           // tf32
__device__ float g_xc[(size_t)BATCH * SEQ * EDIM];            // x as tf32
__device__ float g_wqkv[(size_t)3 * EDIM * EDIM];             // qkv_w as tf32
__device__ float g_wfc[(size_t)EDIM * EDIM];                  // fc_w as tf32

__device__ __forceinline__ uint32_t f2tf(float f) {
    uint32_t u;
    asm("cvt.rna.tf32.f32 %0, %1;" : "=r"(u) : "f"(f));
    return u;
}

__device__ __forceinline__ float ex2f(float x) {
    float y;
    asm("ex2.approx.ftz.f32 %0, %1;" : "=f"(y) : "f"(x));
    return y;
}

__device__ __forceinline__ uint32_t smem_u32(const void* p) {
    return (uint32_t)__cvta_generic_to_shared(p);
}

#define CP_A16(dst, src) \
    asm volatile("cp.async.cg.shared.global [%0], [%1], 16;" :: "r"(dst), "l"(src) : "memory")
#define CP_COMMIT() asm volatile("cp.async.commit_group;" ::: "memory")
#define CP_WAIT0()  asm volatile("cp.async.wait_group 0;" ::: "memory")
#define CP_WAIT1()  asm volatile("cp.async.wait_group 1;" ::: "memory")

__device__ __forceinline__ void mma_tf32(float* c, const uint32_t* a, const uint32_t* b) {
    asm volatile(
        "mma.sync.aligned.m16n8k8.row.col.f32.tf32.tf32.f32 "
        "{%0,%1,%2,%3}, {%4,%5,%6,%7}, {%8,%9}, {%0,%1,%2,%3};"
        : "+f"(c[0]), "+f"(c[1]), "+f"(c[2]), "+f"(c[3])
        : "r"(a[0]), "r"(a[1]), "r"(a[2]), "r"(a[3]), "r"(b[0]), "r"(b[1]));
}

// ldmatrix x4: 4 8x4(tf32) blocks; lane groups 0-7/8-15/16-23/24-31 give row addrs.
__device__ __forceinline__ void ldsm_x4(uint32_t& r0, uint32_t& r1,
                                        uint32_t& r2, uint32_t& r3, uint32_t addr) {
    asm volatile("ldmatrix.sync.aligned.m8n8.x4.shared.b16 {%0,%1,%2,%3}, [%4];"
                 : "=r"(r0), "=r"(r1), "=r"(r2), "=r"(r3) : "r"(addr));
}

// ---------------------------------------------------------------------------
// Elementwise fp32 -> tf32 conversion (memory-bound, cheap)
// ---------------------------------------------------------------------------
__global__ void cvt_tf32_kernel(const float* __restrict__ in,
                                float* __restrict__ out, int n4)
{
    int i = blockIdx.x * blockDim.x + threadIdx.x;
    if (i >= n4) return;
    float4 v = ((const float4*)in)[i];
    uint4 o;
    o.x = f2tf(v.x); o.y = f2tf(v.y); o.z = f2tf(v.z); o.w = f2tf(v.w);
    ((uint4*)out)[i] = o;
}

// Scatter one QKV output element with bias + head_mask, stored as tf32.
// V goes TRANSPOSED [b,h,d,s].
__device__ __forceinline__ void store_qkv_elem(int r, int e, float v,
                                               const float* bias, const float* mask) {
    int bb  = r >> 11;            // batch (S=2048)
    int s   = r & (SEQ - 1);
    int h   = e / 192;            // 3*hd = 192 per head
    int rem = e - h * 192;
    int which = rem >> 6;         // 0=q, 1=k, 2=v
    int j   = rem & 63;
    float val = __uint_as_float(f2tf((v + bias[e]) * mask[h]));
    size_t bh = (size_t)(bb * NHEAD + h);
    if (which == 0)      g_q[(bh * SEQ + s) * HDIM + j] = val;
    else if (which == 1) g_k[(bh * SEQ + s) * HDIM + j] = val;
    else                 g_v[(bh * HDIM + j) * SEQ + s] = val;
}

// ---------------------------------------------------------------------------
// tf32 GEMM: C[M,N] = A[M,K] @ W[N,K]^T. Inputs already tf32 in gmem.
// 512 threads (16 warps, 4x4 grid, warp tile 32x32) -> acc only 32 regs,
// __launch_bounds__(512,2) => 32 warps/SM. 3-stage cp.async, 1 barrier/K-step.
// BM=BN=128, BK=32; smem row stride 36 (conflict-free LDSM).
// ---------------------------------------------------------------------------
template <int MODE>
__global__ __launch_bounds__(512, 2)
void gemm_tf32_kernel(const float* __restrict__ bias,
                      const float* __restrict__ mask,
                      float* __restrict__ out,
                      int M, int N, int K)
{
    extern __shared__ float smp[];
    const int SA = 128 * 36;               // one operand tile (words)
    const uint32_t smu = smem_u32(smp);

    const int tid  = threadIdx.x;
    const int warp = tid >> 5;
    const int lane = tid & 31;
    const int g    = lane >> 2;
    const int t    = lane & 3;
    const int wm   = warp & 3;        // 0..3 (rows)
    const int wn   = warp >> 2;       // 0..3 (cols)
    const int m0   = blockIdx.y * 128;
    const int n0   = blockIdx.x * 128;

    // ldmatrix per-lane row-address pattern (words), stride 36
    const uint32_t offpat = (uint32_t)(((lane & 8) + (lane & 7)) * 36 + ((lane >> 4) << 2));

    const float* Ap = (MODE == 0) ? (const float*)g_att : (const float*)g_xc;
    const float* Wp = (MODE == 0) ? (const float*)g_wfc : (const float*)g_wqkv;

    const int lrow = tid >> 3;        // 0..63
    const int lcol = (tid & 7) << 2;  // 0,4,...,28

    const float* agp = Ap + (size_t)(m0 + lrow) * K + lcol;
    const float* bgp = Wp + (size_t)(n0 + lrow) * K + lcol;

    auto gissue = [&](int st, int k0) {
        #pragma unroll
        for (int i = 0; i < 2; i++) {
            uint32_t offA = (uint32_t)((st * 2 * SA + (lrow + i * 64) * 36 + lcol) << 2);
            CP_A16(smu + offA,             agp + (size_t)i * 64 * K + k0);
            CP_A16(smu + offA + (SA << 2), bgp + (size_t)i * 64 * K + k0);
        }
        CP_COMMIT();
    };

    float acc[2][4][4] = {};

    const int NK = K / 32;
    gissue(0, 0);
    gissue(1, 32);

    for (int ki = 0; ki < NK; ki++) {
        if (ki + 2 < NK) { CP_WAIT1(); }
        else             { CP_WAIT0(); }
        __syncthreads();
        if (ki + 2 < NK) gissue((ki + 2) % 3, (ki + 2) * 32);

        const uint32_t stA = smu + (((ki % 3) * 2 * SA + wm * 32 * 36 + offpat) << 2);
        const uint32_t stB = smu + (((ki % 3) * 2 * SA + SA + wn * 32 * 36 + offpat) << 2);

        #pragma unroll
        for (int kk = 0; kk < 4; kk++) {
            uint32_t a[2][4];
            uint32_t bb[4][2];
            ldsm_x4(a[0][0], a[0][1], a[0][2], a[0][3], stA + (kk * 8 << 2));
            ldsm_x4(a[1][0], a[1][1], a[1][2], a[1][3], stA + ((16 * 36 + kk * 8) << 2));
            ldsm_x4(bb[0][0], bb[1][0], bb[0][1], bb[1][1], stB + (kk * 8 << 2));
            ldsm_x4(bb[2][0], bb[3][0], bb[2][1], bb[3][1], stB + ((16 * 36 + kk * 8) << 2));
            #pragma unroll
            for (int mi = 0; mi < 2; mi++)
                #pragma unroll
                for (int ni = 0; ni < 4; ni++)
                    mma_tf32(acc[mi][ni], a[mi], bb[ni]);
        }
    }

    // Epilogue
    #pragma unroll
    for (int mi = 0; mi < 2; mi++) {
        #pragma unroll
        for (int ni = 0; ni < 4; ni++) {
            int r0 = m0 + wm * 32 + mi * 16 + g;
            int cc = n0 + wn * 32 + ni * 8 + 2 * t;
            if (MODE == 0) {
                float b0 = bias[cc], b1 = bias[cc + 1];
                out[(size_t)r0 * N + cc]           = acc[mi][ni][0] + b0;
                out[(size_t)r0 * N + cc + 1]       = acc[mi][ni][1] + b1;
                out[(size_t)(r0 + 8) * N + cc]     = acc[mi][ni][2] + b0;
                out[(size_t)(r0 + 8) * N + cc + 1] = acc[mi][ni][3] + b1;
            } else {
                store_qkv_elem(r0,     cc,     acc[mi][ni][0], bias, mask);
                store_qkv_elem(r0,     cc + 1, acc[mi][ni][1], bias, mask);
                store_qkv_elem(r0 + 8, cc,     acc[mi][ni][2], bias, mask);
                store_qkv_elem(r0 + 8, cc + 1, acc[mi][ni][3], bias, mask);
            }
        }
    }
}

// ---------------------------------------------------------------------------
// Flash attention: CTA = (b, h, 128-row q-tile), 256 thr (8 warps x 16 rows).
// LDSM fragment loads; cp.async double-buffered K/V; V pre-transposed.
// smem stride 68 (==4 mod 32 words -> conflict-free LDSM phases).
// ---------------------------------------------------------------------------
__global__ __launch_bounds__(256, 2)
void flash_attn_kernel()
{
    extern __shared__ float sm[];
    const int QT = 128 * 68;      // Q region (reused as P), words
    const int ST = 64 * 68;       // one K or V stage, words
    float* sQ = sm;
    const uint32_t smu = smem_u32(sm);

    const int tid  = threadIdx.x;
    const int warp = tid >> 5;
    const int lane = tid & 31;
    const int g    = lane >> 2;
    const int t    = lane & 3;
    const int qt = blockIdx.x;
    const int h  = blockIdx.y;
    const int b  = blockIdx.z;

    const uint32_t offpat68 = (uint32_t)(((lane & 8) + (lane & 7)) * 68 + ((lane >> 4) << 2));

    const size_t baseQK = ((size_t)(b * NHEAD + h)) * SEQ * HDIM;
    const float* Qg = g_q + baseQK + (size_t)qt * 128 * HDIM;
    const float* Kg = g_k + baseQK;
    const float* Vg = g_v + ((size_t)(b * NHEAD + h)) * HDIM * SEQ;   // [d][s]

    // --- async load Q tile (128x64) ---
    #pragma unroll
    for (int i = 0; i < 8; i++) {
        int id = tid + i * 256;
        int r  = id >> 4;
        int c  = (id & 15) << 2;
        CP_A16(smu + ((r * 68 + c) << 2), Qg + r * HDIM + c);
    }
    CP_COMMIT();

    auto load_kv = [&](int st, int kt) {
        #pragma unroll
        for (int i = 0; i < 4; i++) {
            int id = tid + i * 256;
            int r  = id >> 4;
            int c  = (id & 15) << 2;
            CP_A16(smu + ((QT + st * ST + r * 68 + c) << 2),
                   Kg + ((size_t)kt * 64 + r) * HDIM + c);
            CP_A16(smu + ((QT + 2 * ST + st * ST + r * 68 + c) << 2),
                   Vg + (size_t)r * SEQ + kt * 64 + c);
        }
        CP_COMMIT();
    };

    load_kv(0, 0);
    CP_WAIT1();       // Q group done (KV0 may still be in flight)
    __syncthreads();

    // Extract Q A-fragments via LDSM; sQ region then becomes P.
    uint32_t qa[8][4];
    const int pr = warp * 16 + g;
    const uint32_t qBase = smu + ((warp * 16 * 68 + offpat68) << 2);
    #pragma unroll
    for (int kk = 0; kk < 8; kk++)
        ldsm_x4(qa[kk][0], qa[kk][1], qa[kk][2], qa[kk][3], qBase + (kk * 8 << 2));
    __syncthreads();   // everyone has Q frags before sQ is reused as P

    float oc[8][4] = {};
    float m0 = -1e30f, m1 = -1e30f, l0 = 0.0f, l1 = 0.0f;
    const float LOG2E = 1.4426950408889634f;
    const float SCL   = 0.125f;   // 1/sqrt(64)

    int st = 0;
    for (int kt = 0; kt < SEQ / 64; kt++, st ^= 1) {
        if (kt + 1 < SEQ / 64) { load_kv(st ^ 1, kt + 1); CP_WAIT1(); }
        else                   { CP_WAIT0(); }
        __syncthreads();

        const uint32_t kBase = smu + ((QT + st * ST + offpat68) << 2);
        const uint32_t vBase = smu + ((QT + 2 * ST + st * ST + offpat68) << 2);

        // S = Q @ K^T
        float sc[8][4] = {};
        #pragma unroll
        for (int kk = 0; kk < 8; kk++) {
            uint32_t bb[8][2];
            #pragma unroll
            for (int nb = 0; nb < 4; nb++)
                ldsm_x4(bb[2 * nb][0], bb[2 * nb + 1][0], bb[2 * nb][1], bb[2 * nb + 1][1],
                        kBase + ((nb * 16 * 68 + kk * 8) << 2));
            #pragma unroll
            for (int ni = 0; ni < 8; ni++)
                mma_tf32(sc[ni], qa[kk], bb[ni]);
        }

        // online softmax (rows pr, pr+8)
        #pragma unroll
        for (int ni = 0; ni < 8; ni++)
            #pragma unroll
            for (int j = 0; j < 4; j++) sc[ni][j] *= SCL;

        float mx0 = -1e30f, mx1 = -1e30f;
        #pragma unroll
        for (int ni = 0; ni < 8; ni++) {
            mx0 = fmaxf(mx0, fmaxf(sc[ni][0], sc[ni][1]));
            mx1 = fmaxf(mx1, fmaxf(sc[ni][2], sc[ni][3]));
        }
        mx0 = fmaxf(mx0, __shfl_xor_sync(0xffffffffu, mx0, 1));
        mx0 = fmaxf(mx0, __shfl_xor_sync(0xffffffffu, mx0, 2));
        mx1 = fmaxf(mx1, __shfl_xor_sync(0xffffffffu, mx1, 1));
        mx1 = fmaxf(mx1, __shfl_xor_sync(0xffffffffu, mx1, 2));

        float mn0 = fmaxf(m0, mx0);
        float mn1 = fmaxf(m1, mx1);
        float a0 = ex2f((m0 - mn0) * LOG2E);
        float a1 = ex2f((m1 - mn1) * LOG2E);
        m0 = mn0; m1 = mn1;

        float rs0 = 0.0f, rs1 = 0.0f;
        #pragma unroll
        for (int ni = 0; ni < 8; ni++) {
            sc[ni][0] = ex2f((sc[ni][0] - m0) * LOG2E);
            sc[ni][1] = ex2f((sc[ni][1] - m0) * LOG2E);
            sc[ni][2] = ex2f((sc[ni][2] - m1) * LOG2E);
            sc[ni][3] = ex2f((sc[ni][3] - m1) * LOG2E);
            rs0 += sc[ni][0] + sc[ni][1];
            rs1 += sc[ni][2] + sc[ni][3];
        }
        rs0 += __shfl_xor_sync(0xffffffffu, rs0, 1);
        rs0 += __shfl_xor_sync(0xffffffffu, rs0, 2);
        rs1 += __shfl_xor_sync(0xffffffffu, rs1, 1);
        rs1 += __shfl_xor_sync(0xffffffffu, rs1, 2);
        l0 = l0 * a0 + rs0;
        l1 = l1 * a1 + rs1;

        #pragma unroll
        for (int ni = 0; ni < 8; ni++) {
            oc[ni][0] *= a0; oc[ni][1] *= a0;
            oc[ni][2] *= a1; oc[ni][3] *= a1;
        }

        // store P as tf32 (warp-private rows of sQ region)
        #pragma unroll
        for (int ni = 0; ni < 8; ni++) {
            int cc = ni * 8 + 2 * t;
            sQ[pr * 68 + cc]           = __uint_as_float(f2tf(sc[ni][0]));
            sQ[pr * 68 + cc + 1]       = __uint_as_float(f2tf(sc[ni][1]));
            sQ[(pr + 8) * 68 + cc]     = __uint_as_float(f2tf(sc[ni][2]));
            sQ[(pr + 8) * 68 + cc + 1] = __uint_as_float(f2tf(sc[ni][3]));
        }
        __syncwarp();

        // O += P @ V   (V transposed: cV[d][kpos])
        #pragma unroll
        for (int kk = 0; kk < 8; kk++) {
            uint32_t pa[4];
            ldsm_x4(pa[0], pa[1], pa[2], pa[3], qBase + (kk * 8 << 2));
            uint32_t bb[8][2];
            #pragma unroll
            for (int nb = 0; nb < 4; nb++)
                ldsm_x4(bb[2 * nb][0], bb[2 * nb + 1][0], bb[2 * nb][1], bb[2 * nb + 1][1],
                        vBase + ((nb * 16 * 68 + kk * 8) << 2));
            #pragma unroll
            for (int ni = 0; ni < 8; ni++)
                mma_tf32(oc[ni], pa, bb[ni]);
        }
        __syncthreads();
    }

    // epilogue: normalize, write g_att (tf32) as [B, S, H*hd]
    float i0 = 1.0f / l0;
    float i1 = 1.0f / l1;
    int r0 = qt * 128 + warp * 16 + g;
    float* Og = g_att + (size_t)b * SEQ * EDIM + (size_t)h * HDIM;
    #pragma unroll
    for (int ni = 0; ni < 8; ni++) {
        int cc = ni * 8 + 2 * t;
        Og[(size_t)r0 * EDIM + cc]           = __uint_as_float(f2tf(oc[ni][0] * i0));
        Og[(size_t)r0 * EDIM + cc + 1]       = __uint_as_float(f2tf(oc[ni][1] * i0));
        Og[(size_t)(r0 + 8) * EDIM + cc]     = __uint_as_float(f2tf(oc[ni][2] * i1));
        Og[(size_t)(r0 + 8) * EDIM + cc + 1] = __uint_as_float(f2tf(oc[ni][3] * i1));
    }
}

extern "C" void kernel_launch(void* const* d_in, const int* in_sizes, int n_in,
                              void* d_out, int out_size)
{
    const float* x     = (const float*)d_in[0];
    const float* hmask = (const float*)d_in[1];
    const float* qkv_w = (const float*)d_in[2];
    const float* qkv_b = (const float*)d_in[3];
    const float* fc_w  = (const float*)d_in[4];
    const float* fc_b  = (const float*)d_in[5];
    float* out = (float*)d_out;

    const int gemm_smem = 3 * 2 * 128 * 36 * (int)sizeof(float);         // 110592
    const int fa_smem   = (128 * 68 + 4 * 64 * 68) * (int)sizeof(float); // 104448

    cudaFuncSetAttribute(gemm_tf32_kernel<1>,
                         cudaFuncAttributeMaxDynamicSharedMemorySize, gemm_smem);
    cudaFuncSetAttribute(gemm_tf32_kernel<0>,
                         cudaFuncAttributeMaxDynamicSharedMemorySize, gemm_smem);
    cudaFuncSetAttribute(flash_attn_kernel,
                         cudaFuncAttributeMaxDynamicSharedMemorySize, fa_smem);

    float* xc   = nullptr; cudaGetSymbolAddress((void**)&xc,   g_xc);
    float* wqkv = nullptr; cudaGetSymbolAddress((void**)&wqkv, g_wqkv);
    float* wfc  = nullptr; cudaGetSymbolAddress((void**)&wfc,  g_wfc);

    // 0) pre-convert operands to tf32 (memory-bound, cheap)
    cvt_tf32_kernel<<<(BATCH * SEQ * EDIM / 4 + 255) / 256, 256>>>(x, xc, BATCH * SEQ * EDIM / 4);
    cvt_tf32_kernel<<<(3 * EDIM * EDIM / 4 + 255) / 256, 256>>>(qkv_w, wqkv, 3 * EDIM * EDIM / 4);
    cvt_tf32_kernel<<<(EDIM * EDIM / 4 + 255) / 256, 256>>>(fc_w, wfc, EDIM * EDIM / 4);

    // 1) QKV projection + bias + head_mask + scatter (q/k tf32, v tf32 transposed)
    gemm_tf32_kernel<1><<<dim3(3 * EDIM / 128, BATCH * SEQ / 128), 512, gemm_smem>>>(
        qkv_b, hmask, nullptr, BATCH * SEQ, 3 * EDIM, EDIM);

    // 2) flash attention -> g_att [B,S,D] (tf32)
    flash_attn_kernel<<<dim3(SEQ / 128, NHEAD, BATCH), 256, fa_smem>>>();

    // 3) output projection + bias -> d_out (fp32)
    gemm_tf32_kernel<0><<<dim3(EDIM / 128, BATCH * SEQ / 128), 512, gemm_smem>>>(
        fc_b, nullptr, out, BATCH * SEQ, EDIM, EDIM);
}

// round 8
// speedup vs baseline: 1.7937x; 1.7937x over previous
#include <cuda_runtime.h>
#include <cuda_fp16.h>
#include <cstdint>

#define BATCH 2
#define SEQ   2048
#define NHEAD 16
#define HDIM  64
#define EDIM  1024

// Scratch (static device globals: allocation-free per harness rules)
__device__ __align__(16) __half g_q[(size_t)BATCH * NHEAD * SEQ * HDIM];
__device__ __align__(16) __half g_k[(size_t)BATCH * NHEAD * SEQ * HDIM];
__device__ __align__(16) __half g_v[(size_t)BATCH * NHEAD * SEQ * HDIM];  // TRANSPOSED [b,h,d,s]
__device__ __align__(16) __half g_att[(size_t)BATCH * SEQ * EDIM];
__device__ __align__(16) __half g_xc[(size_t)BATCH * SEQ * EDIM];
__device__ __align__(16) __half g_wqkv[(size_t)3 * EDIM * EDIM];
__device__ __align__(16) __half g_wfc[(size_t)EDIM * EDIM];

__device__ __forceinline__ float ex2f(float x) {
    float y;
    asm("ex2.approx.ftz.f32 %0, %1;" : "=f"(y) : "f"(x));
    return y;
}

__device__ __forceinline__ uint32_t smem_u32(const void* p) {
    return (uint32_t)__cvta_generic_to_shared(p);
}

#define CP_A16(dst, src) \
    asm volatile("cp.async.cg.shared.global [%0], [%1], 16;" :: "r"(dst), "l"(src) : "memory")
#define CP_COMMIT() asm volatile("cp.async.commit_group;" ::: "memory")
#define CP_WAIT0()  asm volatile("cp.async.wait_group 0;" ::: "memory")
#define CP_WAIT1()  asm volatile("cp.async.wait_group 1;" ::: "memory")

// fp16 MMA, fp32 accumulate: D[16x8] += A[16x16] * B[16x8]
__device__ __forceinline__ void mma_f16(float* c, const uint32_t* a, const uint32_t* b) {
    asm volatile(
        "mma.sync.aligned.m16n8k16.row.col.f32.f16.f16.f32 "
        "{%0,%1,%2,%3}, {%4,%5,%6,%7}, {%8,%9}, {%0,%1,%2,%3};"
        : "+f"(c[0]), "+f"(c[1]), "+f"(c[2]), "+f"(c[3])
        : "r"(a[0]), "r"(a[1]), "r"(a[2]), "r"(a[3]), "r"(b[0]), "r"(b[1]));
}

// ldmatrix x4 (b16): 4 8x8 fp16 blocks; lane groups 0-7/8-15/16-23/24-31 give row addrs.
__device__ __forceinline__ void ldsm_x4(uint32_t& r0, uint32_t& r1,
                                        uint32_t& r2, uint32_t& r3, uint32_t addr) {
    asm volatile("ldmatrix.sync.aligned.m8n8.x4.shared.b16 {%0,%1,%2,%3}, [%4];"
                 : "=r"(r0), "=r"(r1), "=r"(r2), "=r"(r3) : "r"(addr));
}

// ---------------------------------------------------------------------------
// Elementwise fp32 -> fp16 conversion (memory-bound, cheap)
// ---------------------------------------------------------------------------
__global__ void cvt_f16_kernel(const float* __restrict__ in,
                               __half* __restrict__ out, int n4)
{
    int i = blockIdx.x * blockDim.x + threadIdx.x;
    if (i >= n4) return;
    float4 v = ((const float4*)in)[i];
    __half2* o = (__half2*)out;
    o[2 * i]     = __floats2half2_rn(v.x, v.y);
    o[2 * i + 1] = __floats2half2_rn(v.z, v.w);
}

// Scatter one QKV output element with bias + head_mask, stored as fp16.
// V goes TRANSPOSED [b,h,d,s].
__device__ __forceinline__ void store_qkv_elem(int r, int e, float v,
                                               const float* bias, const float* mask) {
    int bb  = r >> 11;            // batch (S=2048)
    int s   = r & (SEQ - 1);
    int h   = e / 192;            // 3*hd = 192 per head
    int rem = e - h * 192;
    int which = rem >> 6;         // 0=q, 1=k, 2=v
    int j   = rem & 63;
    __half val = __float2half_rn((v + bias[e]) * mask[h]);
    size_t bh = (size_t)(bb * NHEAD + h);
    if (which == 0)      g_q[(bh * SEQ + s) * HDIM + j] = val;
    else if (which == 1) g_k[(bh * SEQ + s) * HDIM + j] = val;
    else                 g_v[(bh * HDIM + j) * SEQ + s] = val;
}

// ---------------------------------------------------------------------------
// fp16 GEMM: C[M,N] = A[M,K] @ W[N,K]^T, fp32 accumulate.
// BM=BN=128, BK=64; 256 thr (4x2 warps, 32x64 warp tile); 3-stage cp.async,
// 1 barrier per K-step. smem row = 64 halves + 8 pad = 144B (CF ldmatrix).
// ---------------------------------------------------------------------------
template <int MODE>
__global__ __launch_bounds__(256, 2)
void gemm_f16_kernel(const float* __restrict__ bias,
                     const float* __restrict__ mask,
                     float* __restrict__ out,
                     int M, int N, int K)
{
    extern __shared__ __half smh[];
    const int TILEB = 128 * 144;           // one operand tile, bytes
    const uint32_t smu = smem_u32(smh);

    const int tid  = threadIdx.x;
    const int warp = tid >> 5;
    const int lane = tid & 31;
    const int g    = lane >> 2;
    const int t    = lane & 3;
    const int wm   = warp >> 1;       // 0..3
    const int wn   = warp & 1;        // 0..1
    const int m0   = blockIdx.y * 128;
    const int n0   = blockIdx.x * 128;

    // ldmatrix per-lane row-address pattern (bytes), row stride 144
    const uint32_t offpat = (uint32_t)(((lane & 8) + (lane & 7)) * 144 + ((lane >> 4) << 4));

    const __half* Ap = (MODE == 0) ? (const __half*)g_att : (const __half*)g_xc;
    const __half* Wp = (MODE == 0) ? (const __half*)g_wfc : (const __half*)g_wqkv;

    auto gissue = [&](int st, int k0) {
        #pragma unroll
        for (int i = 0; i < 4; i++) {
            int idx = tid + i * 256;
            int row = idx >> 3;            // 0..127
            int cp  = (idx & 7) << 3;      // halves offset, 16B chunks
            uint32_t dst = (uint32_t)(st * 2 * TILEB + row * 144 + cp * 2);
            CP_A16(smu + dst,         Ap + (size_t)(m0 + row) * K + k0 + cp);
            CP_A16(smu + dst + TILEB, Wp + (size_t)(n0 + row) * K + k0 + cp);
        }
        CP_COMMIT();
    };

    float acc[2][8][4] = {};

    const int NK = K / 64;
    gissue(0, 0);
    gissue(1, 64);

    for (int ki = 0; ki < NK; ki++) {
        if (ki + 2 < NK) { CP_WAIT1(); }
        else             { CP_WAIT0(); }
        __syncthreads();
        if (ki + 2 < NK) gissue((ki + 2) % 3, (ki + 2) * 64);

        const uint32_t stA = smu + (uint32_t)((ki % 3) * 2 * TILEB + wm * 32 * 144) + offpat;
        const uint32_t stB = smu + (uint32_t)((ki % 3) * 2 * TILEB + TILEB + wn * 64 * 144) + offpat;

        #pragma unroll
        for (int kk = 0; kk < 4; kk++) {       // K=64 -> 4 x k16
            uint32_t a[2][4];
            uint32_t bb[8][2];
            ldsm_x4(a[0][0], a[0][1], a[0][2], a[0][3], stA + kk * 32);
            ldsm_x4(a[1][0], a[1][1], a[1][2], a[1][3], stA + 16 * 144 + kk * 32);
            #pragma unroll
            for (int nb = 0; nb < 4; nb++)
                ldsm_x4(bb[2 * nb][0], bb[2 * nb + 1][0], bb[2 * nb][1], bb[2 * nb + 1][1],
                        stB + nb * 16 * 144 + kk * 32);
            #pragma unroll
            for (int mi = 0; mi < 2; mi++)
                #pragma unroll
                for (int ni = 0; ni < 8; ni++)
                    mma_f16(acc[mi][ni], a[mi], bb[ni]);
        }
    }

    // Epilogue
    #pragma unroll
    for (int mi = 0; mi < 2; mi++) {
        #pragma unroll
        for (int ni = 0; ni < 8; ni++) {
            int r0 = m0 + wm * 32 + mi * 16 + g;
            int cc = n0 + wn * 64 + ni * 8 + 2 * t;
            if (MODE == 0) {
                float b0 = bias[cc], b1 = bias[cc + 1];
                out[(size_t)r0 * N + cc]           = acc[mi][ni][0] + b0;
                out[(size_t)r0 * N + cc + 1]       = acc[mi][ni][1] + b1;
                out[(size_t)(r0 + 8) * N + cc]     = acc[mi][ni][2] + b0;
                out[(size_t)(r0 + 8) * N + cc + 1] = acc[mi][ni][3] + b1;
            } else {
                store_qkv_elem(r0,     cc,     acc[mi][ni][0], bias, mask);
                store_qkv_elem(r0,     cc + 1, acc[mi][ni][1], bias, mask);
                store_qkv_elem(r0 + 8, cc,     acc[mi][ni][2], bias, mask);
                store_qkv_elem(r0 + 8, cc + 1, acc[mi][ni][3], bias, mask);
            }
        }
    }
}

// ---------------------------------------------------------------------------
// Flash attention (fp16 operands, fp32 softmax/acc): CTA = (b,h,128-row q-tile),
// 256 thr. cp.async double-buffered K/V; V pre-transposed; row stride 144B.
// ---------------------------------------------------------------------------
__global__ __launch_bounds__(256, 2)
void flash_attn_kernel()
{
    extern __shared__ __half smh[];
    const int QTB = 128 * 144;    // Q region bytes (reused as P)
    const int STB = 64 * 144;     // one K or V stage, bytes
    __half* sQh = smh;            // P stores go through this
    const uint32_t smu = smem_u32(smh);

    const int tid  = threadIdx.x;
    const int warp = tid >> 5;
    const int lane = tid & 31;
    const int g    = lane >> 2;
    const int t    = lane & 3;
    const int qt = blockIdx.x;
    const int h  = blockIdx.y;
    const int b  = blockIdx.z;

    const uint32_t offpat = (uint32_t)(((lane & 8) + (lane & 7)) * 144 + ((lane >> 4) << 4));

    const size_t baseQK = ((size_t)(b * NHEAD + h)) * SEQ * HDIM;
    const __half* Qg = g_q + baseQK + (size_t)qt * 128 * HDIM;
    const __half* Kg = g_k + baseQK;
    const __half* Vg = g_v + ((size_t)(b * NHEAD + h)) * HDIM * SEQ;   // [d][s]

    // --- async load Q tile (128 x 64 halves) ---
    #pragma unroll
    for (int i = 0; i < 4; i++) {
        int idx = tid + i * 256;
        int row = idx >> 3;
        int cp  = (idx & 7) << 3;     // halves
        CP_A16(smu + (uint32_t)(row * 144 + cp * 2), Qg + row * HDIM + cp);
    }
    CP_COMMIT();

    auto load_kv = [&](int st, int kt) {
        #pragma unroll
        for (int i = 0; i < 2; i++) {
            int idx = tid + i * 256;
            int row = idx >> 3;           // 0..63
            int cp  = (idx & 7) << 3;
            CP_A16(smu + (uint32_t)(QTB + st * STB + row * 144 + cp * 2),
                   Kg + ((size_t)kt * 64 + row) * HDIM + cp);
            CP_A16(smu + (uint32_t)(QTB + 2 * STB + st * STB + row * 144 + cp * 2),
                   Vg + (size_t)row * SEQ + kt * 64 + cp);
        }
        CP_COMMIT();
    };

    load_kv(0, 0);
    CP_WAIT1();       // Q group done (KV0 may still be in flight)
    __syncthreads();

    // Extract Q A-fragments via LDSM; sQ region then becomes P.
    uint32_t qa[4][4];
    const int pr = warp * 16 + g;
    const uint32_t qBase = smu + (uint32_t)(warp * 16 * 144) + offpat;
    #pragma unroll
    for (int kk = 0; kk < 4; kk++)
        ldsm_x4(qa[kk][0], qa[kk][1], qa[kk][2], qa[kk][3], qBase + kk * 32);
    __syncthreads();   // everyone has Q frags before sQ is reused as P

    float oc[8][4] = {};
    float m0 = -1e30f, m1 = -1e30f, l0 = 0.0f, l1 = 0.0f;
    const float LOG2E = 1.4426950408889634f;
    const float SCL   = 0.125f;   // 1/sqrt(64)

    int st = 0;
    for (int kt = 0; kt < SEQ / 64; kt++, st ^= 1) {
        if (kt + 1 < SEQ / 64) { load_kv(st ^ 1, kt + 1); CP_WAIT1(); }
        else                   { CP_WAIT0(); }
        __syncthreads();

        const uint32_t kBase = smu + (uint32_t)(QTB + st * STB) + offpat;
        const uint32_t vBase = smu + (uint32_t)(QTB + 2 * STB + st * STB) + offpat;

        // S = Q @ K^T  (this warp: its 16 rows x 64 kv-cols)
        float sc[8][4] = {};
        #pragma unroll
        for (int kk = 0; kk < 4; kk++) {
            uint32_t bb[8][2];
            #pragma unroll
            for (int nb = 0; nb < 4; nb++)
                ldsm_x4(bb[2 * nb][0], bb[2 * nb + 1][0], bb[2 * nb][1], bb[2 * nb + 1][1],
                        kBase + nb * 16 * 144 + kk * 32);
            #pragma unroll
            for (int ni = 0; ni < 8; ni++)
                mma_f16(sc[ni], qa[kk], bb[ni]);
        }

        // online softmax (rows pr, pr+8)
        #pragma unroll
        for (int ni = 0; ni < 8; ni++)
            #pragma unroll
            for (int j = 0; j < 4; j++) sc[ni][j] *= SCL;

        float mx0 = -1e30f, mx1 = -1e30f;
        #pragma unroll
        for (int ni = 0; ni < 8; ni++) {
            mx0 = fmaxf(mx0, fmaxf(sc[ni][0], sc[ni][1]));
            mx1 = fmaxf(mx1, fmaxf(sc[ni][2], sc[ni][3]));
        }
        mx0 = fmaxf(mx0, __shfl_xor_sync(0xffffffffu, mx0, 1));
        mx0 = fmaxf(mx0, __shfl_xor_sync(0xffffffffu, mx0, 2));
        mx1 = fmaxf(mx1, __shfl_xor_sync(0xffffffffu, mx1, 1));
        mx1 = fmaxf(mx1, __shfl_xor_sync(0xffffffffu, mx1, 2));

        float mn0 = fmaxf(m0, mx0);
        float mn1 = fmaxf(m1, mx1);
        float a0 = ex2f((m0 - mn0) * LOG2E);
        float a1 = ex2f((m1 - mn1) * LOG2E);
        m0 = mn0; m1 = mn1;

        float rs0 = 0.0f, rs1 = 0.0f;
        #pragma unroll
        for (int ni = 0; ni < 8; ni++) {
            sc[ni][0] = ex2f((sc[ni][0] - m0) * LOG2E);
            sc[ni][1] = ex2f((sc[ni][1] - m0) * LOG2E);
            sc[ni][2] = ex2f((sc[ni][2] - m1) * LOG2E);
            sc[ni][3] = ex2f((sc[ni][3] - m1) * LOG2E);
            rs0 += sc[ni][0] + sc[ni][1];
            rs1 += sc[ni][2] + sc[ni][3];
        }
        rs0 += __shfl_xor_sync(0xffffffffu, rs0, 1);
        rs0 += __shfl_xor_sync(0xffffffffu, rs0, 2);
        rs1 += __shfl_xor_sync(0xffffffffu, rs1, 1);
        rs1 += __shfl_xor_sync(0xffffffffu, rs1, 2);
        l0 = l0 * a0 + rs0;
        l1 = l1 * a1 + rs1;

        #pragma unroll
        for (int ni = 0; ni < 8; ni++) {
            oc[ni][0] *= a0; oc[ni][1] *= a0;
            oc[ni][2] *= a1; oc[ni][3] *= a1;
        }

        // store P as fp16 (warp-private rows of sQ region)
        #pragma unroll
        for (int ni = 0; ni < 8; ni++) {
            int cc = ni * 8 + 2 * t;
            *(__half2*)(sQh + pr * 72 + cc)       = __floats2half2_rn(sc[ni][0], sc[ni][1]);
            *(__half2*)(sQh + (pr + 8) * 72 + cc) = __floats2half2_rn(sc[ni][2], sc[ni][3]);
        }
        __syncwarp();

        // O += P @ V   (V transposed: rows = d)
        #pragma unroll
        for (int kk = 0; kk < 4; kk++) {
            uint32_t pa[4];
            ldsm_x4(pa[0], pa[1], pa[2], pa[3], qBase + kk * 32);
            uint32_t bb[8][2];
            #pragma unroll
            for (int nb = 0; nb < 4; nb++)
                ldsm_x4(bb[2 * nb][0], bb[2 * nb + 1][0], bb[2 * nb][1], bb[2 * nb + 1][1],
                        vBase + nb * 16 * 144 + kk * 32);
            #pragma unroll
            for (int ni = 0; ni < 8; ni++)
                mma_f16(oc[ni], pa, bb[ni]);
        }
        __syncthreads();
    }

    // epilogue: normalize, write g_att (fp16) as [B, S, H*hd]
    float i0 = 1.0f / l0;
    float i1 = 1.0f / l1;
    int r0 = qt * 128 + warp * 16 + g;
    __half* Og = g_att + (size_t)b * SEQ * EDIM + (size_t)h * HDIM;
    #pragma unroll
    for (int ni = 0; ni < 8; ni++) {
        int cc = ni * 8 + 2 * t;
        *(__half2*)(Og + (size_t)r0 * EDIM + cc) =
            __floats2half2_rn(oc[ni][0] * i0, oc[ni][1] * i0);
        *(__half2*)(Og + (size_t)(r0 + 8) * EDIM + cc) =
            __floats2half2_rn(oc[ni][2] * i1, oc[ni][3] * i1);
    }
}

extern "C" void kernel_launch(void* const* d_in, const int* in_sizes, int n_in,
                              void* d_out, int out_size)
{
    const float* x     = (const float*)d_in[0];
    const float* hmask = (const float*)d_in[1];
    const float* qkv_w = (const float*)d_in[2];
    const float* qkv_b = (const float*)d_in[3];
    const float* fc_w  = (const float*)d_in[4];
    const float* fc_b  = (const float*)d_in[5];
    float* out = (float*)d_out;

    const int gemm_smem = 3 * 2 * 128 * 144;                 // 110592 B
    const int fa_smem   = 128 * 144 + 4 * 64 * 144;          // 55296 B

    cudaFuncSetAttribute(gemm_f16_kernel<1>,
                         cudaFuncAttributeMaxDynamicSharedMemorySize, gemm_smem);
    cudaFuncSetAttribute(gemm_f16_kernel<0>,
                         cudaFuncAttributeMaxDynamicSharedMemorySize, gemm_smem);
    cudaFuncSetAttribute(flash_attn_kernel,
                         cudaFuncAttributeMaxDynamicSharedMemorySize, fa_smem);

    __half* xc   = nullptr; cudaGetSymbolAddress((void**)&xc,   g_xc);
    __half* wqkv = nullptr; cudaGetSymbolAddress((void**)&wqkv, g_wqkv);
    __half* wfc  = nullptr; cudaGetSymbolAddress((void**)&wfc,  g_wfc);

    // 0) pre-convert operands to fp16 (memory-bound, cheap)
    cvt_f16_kernel<<<(BATCH * SEQ * EDIM / 4 + 255) / 256, 256>>>(x, xc, BATCH * SEQ * EDIM / 4);
    cvt_f16_kernel<<<(3 * EDIM * EDIM / 4 + 255) / 256, 256>>>(qkv_w, wqkv, 3 * EDIM * EDIM / 4);
    cvt_f16_kernel<<<(EDIM * EDIM / 4 + 255) / 256, 256>>>(fc_w, wfc, EDIM * EDIM / 4);

    // 1) QKV projection + bias + head_mask + scatter (q/k fp16, v fp16 transposed)
    gemm_f16_kernel<1><<<dim3(3 * EDIM / 128, BATCH * SEQ / 128), 256, gemm_smem>>>(
        qkv_b, hmask, nullptr, BATCH * SEQ, 3 * EDIM, EDIM);

    // 2) flash attention -> g_att [B,S,D] (fp16)
    flash_attn_kernel<<<dim3(SEQ / 128, NHEAD, BATCH), 256, fa_smem>>>();

    // 3) output projection + bias -> d_out (fp32)
    gemm_f16_kernel<0><<<dim3(EDIM / 128, BATCH * SEQ / 128), 256, gemm_smem>>>(
        fc_b, nullptr, out, BATCH * SEQ, EDIM, EDIM);
}

// round 10
// speedup vs baseline: 1.8144x; 1.0116x over previous
#include <cuda_runtime.h>
#include <cuda_fp16.h>
#include <cstdint>

#define BATCH 2
#define SEQ   2048
#define NHEAD 16
#define HDIM  64
#define EDIM  1024

// Scratch (static device globals: allocation-free per harness rules)
__device__ __align__(16) __half g_q[(size_t)BATCH * NHEAD * SEQ * HDIM];
__device__ __align__(16) __half g_k[(size_t)BATCH * NHEAD * SEQ * HDIM];
__device__ __align__(16) __half g_v[(size_t)BATCH * NHEAD * SEQ * HDIM];  // TRANSPOSED [b,h,d,s]
__device__ __align__(16) __half g_att[(size_t)BATCH * SEQ * EDIM];
__device__ __align__(16) __half g_xc[(size_t)BATCH * SEQ * EDIM];
__device__ __align__(16) __half g_wqkv[(size_t)3 * EDIM * EDIM];
__device__ __align__(16) __half g_wfc[(size_t)EDIM * EDIM];

__device__ __forceinline__ float ex2f(float x) {
    float y;
    asm("ex2.approx.ftz.f32 %0, %1;" : "=f"(y) : "f"(x));
    return y;
}

__device__ __forceinline__ uint32_t smem_u32(const void* p) {
    return (uint32_t)__cvta_generic_to_shared(p);
}

#define CP_A16(dst, src) \
    asm volatile("cp.async.cg.shared.global [%0], [%1], 16;" :: "r"(dst), "l"(src) : "memory")
#define CP_COMMIT() asm volatile("cp.async.commit_group;" ::: "memory")
#define CP_WAIT0()  asm volatile("cp.async.wait_group 0;" ::: "memory")
#define CP_WAIT1()  asm volatile("cp.async.wait_group 1;" ::: "memory")
#define CP_WAIT2()  asm volatile("cp.async.wait_group 2;" ::: "memory")

// fp16 MMA, fp32 accumulate: D[16x8] += A[16x16] * B[16x8]
__device__ __forceinline__ void mma_f16(float* c, const uint32_t* a, const uint32_t* b) {
    asm volatile(
        "mma.sync.aligned.m16n8k16.row.col.f32.f16.f16.f32 "
        "{%0,%1,%2,%3}, {%4,%5,%6,%7}, {%8,%9}, {%0,%1,%2,%3};"
        : "+f"(c[0]), "+f"(c[1]), "+f"(c[2]), "+f"(c[3])
        : "r"(a[0]), "r"(a[1]), "r"(a[2]), "r"(a[3]), "r"(b[0]), "r"(b[1]));
}

__device__ __forceinline__ void ldsm_x4(uint32_t& r0, uint32_t& r1,
                                        uint32_t& r2, uint32_t& r3, uint32_t addr) {
    asm volatile("ldmatrix.sync.aligned.m8n8.x4.shared.b16 {%0,%1,%2,%3}, [%4];"
                 : "=r"(r0), "=r"(r1), "=r"(r2), "=r"(r3) : "r"(addr));
}

// ---------------------------------------------------------------------------
// Fused fp32 -> fp16 conversion of x, qkv_w, fc_w in ONE launch.
// ---------------------------------------------------------------------------
#define N4_X  (BATCH * SEQ * EDIM / 4)       // 1048576
#define N4_WQ (3 * EDIM * EDIM / 4)          //  786432
#define N4_WF (EDIM * EDIM / 4)              //  262144

__global__ void cvt_all_kernel(const float* __restrict__ x,
                               const float* __restrict__ wq,
                               const float* __restrict__ wf)
{
    int i = blockIdx.x * blockDim.x + threadIdx.x;
    const float* src;
    __half* dst;
    int j;
    if (i < N4_X)                { src = x;  dst = g_xc;   j = i; }
    else if (i < N4_X + N4_WQ)   { src = wq; dst = g_wqkv; j = i - N4_X; }
    else if (i < N4_X + N4_WQ + N4_WF) { src = wf; dst = g_wfc; j = i - N4_X - N4_WQ; }
    else return;
    float4 v = ((const float4*)src)[j];
    __half2* o = (__half2*)dst;
    o[2 * j]     = __floats2half2_rn(v.x, v.y);
    o[2 * j + 1] = __floats2half2_rn(v.z, v.w);
}

// ---------------------------------------------------------------------------
// fp16 GEMM: C[M,N] = A[M,K] @ W[N,K]^T, fp32 accumulate. PERSISTENT CTAs.
// BM=BN=128, BK=64; 256 thr (4x2 warps, 32x64 warp tile); 3-stage cp.async,
// 1 barrier per K-step. smem row = 64 halves + 8 pad = 144B (CF ldmatrix).
// MODE 0: out = C + bias (fp32). MODE 1: QKV scatter epilogue (half2 q/k,
// transposed V), column attrs hoisted per 8-col block.
// ---------------------------------------------------------------------------
template <int MODE>
__global__ __launch_bounds__(256, 2)
void gemm_f16_kernel(const float* __restrict__ bias,
                     const float* __restrict__ mask,
                     float* __restrict__ out,
                     int M, int N, int K, int NT, int NBX)
{
    extern __shared__ __half smh[];
    const int TILEB = 128 * 144;           // one operand tile, bytes
    const uint32_t smu = smem_u32(smh);

    const int tid  = threadIdx.x;
    const int warp = tid >> 5;
    const int lane = tid & 31;
    const int g    = lane >> 2;
    const int t    = lane & 3;
    const int wm   = warp >> 1;       // 0..3
    const int wn   = warp & 1;        // 0..1

    const uint32_t offpat = (uint32_t)(((lane & 8) + (lane & 7)) * 144 + ((lane >> 4) << 4));

    const __half* Ap = (MODE == 0) ? (const __half*)g_att : (const __half*)g_xc;
    const __half* Wp = (MODE == 0) ? (const __half*)g_wfc : (const __half*)g_wqkv;

    for (int tile = blockIdx.x; tile < NT; tile += gridDim.x) {
        const int m0 = (tile / NBX) * 128;
        const int n0 = (tile % NBX) * 128;

        auto gissue = [&](int st, int k0) {
            #pragma unroll
            for (int i = 0; i < 4; i++) {
                int idx = tid + i * 256;
                int row = idx >> 3;            // 0..127
                int cp  = (idx & 7) << 3;      // halves offset, 16B chunks
                uint32_t dst = (uint32_t)(st * 2 * TILEB + row * 144 + cp * 2);
                CP_A16(smu + dst,         Ap + (size_t)(m0 + row) * K + k0 + cp);
                CP_A16(smu + dst + TILEB, Wp + (size_t)(n0 + row) * K + k0 + cp);
            }
            CP_COMMIT();
        };

        float acc[2][8][4] = {};

        const int NK = K / 64;
        gissue(0, 0);
        gissue(1, 64);

        for (int ki = 0; ki < NK; ki++) {
            if (ki + 2 < NK) { CP_WAIT1(); }
            else             { CP_WAIT0(); }
            __syncthreads();
            if (ki + 2 < NK) gissue((ki + 2) % 3, (ki + 2) * 64);

            const uint32_t stA = smu + (uint32_t)((ki % 3) * 2 * TILEB + wm * 32 * 144) + offpat;
            const uint32_t stB = smu + (uint32_t)((ki % 3) * 2 * TILEB + TILEB + wn * 64 * 144) + offpat;

            #pragma unroll
            for (int kk = 0; kk < 4; kk++) {       // K=64 -> 4 x k16
                uint32_t a[2][4];
                uint32_t bb[8][2];
                ldsm_x4(a[0][0], a[0][1], a[0][2], a[0][3], stA + kk * 32);
                ldsm_x4(a[1][0], a[1][1], a[1][2], a[1][3], stA + 16 * 144 + kk * 32);
                #pragma unroll
                for (int nb = 0; nb < 4; nb++)
                    ldsm_x4(bb[2 * nb][0], bb[2 * nb + 1][0], bb[2 * nb][1], bb[2 * nb + 1][1],
                            stB + nb * 16 * 144 + kk * 32);
                #pragma unroll
                for (int mi = 0; mi < 2; mi++)
                    #pragma unroll
                    for (int ni = 0; ni < 8; ni++)
                        mma_f16(acc[mi][ni], a[mi], bb[ni]);
            }
        }

        // Epilogue: column attributes hoisted per ni (8-col block is within one
        // 64-aligned chunk -> single h/which for the block).
        #pragma unroll
        for (int ni = 0; ni < 8; ni++) {
            const int base8 = n0 + wn * 64 + ni * 8;
            const int cc    = base8 + 2 * t;
            if (MODE == 0) {
                float b0 = bias[cc], b1 = bias[cc + 1];
                #pragma unroll
                for (int mi = 0; mi < 2; mi++) {
                    int r0 = m0 + wm * 32 + mi * 16 + g;
                    out[(size_t)r0 * N + cc]           = acc[mi][ni][0] + b0;
                    out[(size_t)r0 * N + cc + 1]       = acc[mi][ni][1] + b1;
                    out[(size_t)(r0 + 8) * N + cc]     = acc[mi][ni][2] + b0;
                    out[(size_t)(r0 + 8) * N + cc + 1] = acc[mi][ni][3] + b1;
                }
            } else {
                const int h     = base8 / 192;
                const int rem   = base8 - h * 192;
                const int which = rem >> 6;           // 0=q,1=k,2=v
                const int j     = (rem & 63) + 2 * t;
                const float scm = mask[h];
                const float b0  = bias[cc] * scm;     // (v+b)*m == v*m + b*m
                const float b1  = bias[cc + 1] * scm;
                #pragma unroll
                for (int mi = 0; mi < 2; mi++) {
                    #pragma unroll
                    for (int half_ = 0; half_ < 2; half_++) {
                        int r = m0 + wm * 32 + mi * 16 + g + half_ * 8;
                        float v0 = acc[mi][ni][2 * half_]     * scm + b0;
                        float v1 = acc[mi][ni][2 * half_ + 1] * scm + b1;
                        int bb_ = r >> 11;
                        int s   = r & (SEQ - 1);
                        size_t bh = (size_t)(bb_ * NHEAD + h);
                        if (which == 0) {
                            *(__half2*)(g_q + (bh * SEQ + s) * HDIM + j) =
                                __floats2half2_rn(v0, v1);
                        } else if (which == 1) {
                            *(__half2*)(g_k + (bh * SEQ + s) * HDIM + j) =
                                __floats2half2_rn(v0, v1);
                        } else {
                            g_v[(bh * HDIM + j)     * SEQ + s] = __float2half_rn(v0);
                            g_v[(bh * HDIM + j + 1) * SEQ + s] = __float2half_rn(v1);
                        }
                    }
                }
            }
        }
        __syncthreads();   // protect smem stages before next tile's prologue
    }
}

// ---------------------------------------------------------------------------
// Flash attention (fp16 mma.sync, fp32 softmax/acc). PERSISTENT CTAs.
// Logical tile = (b, h, 128-row q-tile); 256 thr; cp.async double-buffered
// K/V; V pre-transposed; row stride 144B.
// ---------------------------------------------------------------------------
__global__ __launch_bounds__(256, 2)
void flash_attn_kernel(int NT)
{
    extern __shared__ __half smh[];
    const int QTB = 128 * 144;    // Q region bytes (reused as P)
    const int STB = 64 * 144;     // one K or V stage, bytes
    __half* sQh = smh;
    const uint32_t smu = smem_u32(smh);

    const int tid  = threadIdx.x;
    const int warp = tid >> 5;
    const int lane = tid & 31;
    const int g    = lane >> 2;
    const int t    = lane & 3;

    const uint32_t offpat = (uint32_t)(((lane & 8) + (lane & 7)) * 144 + ((lane >> 4) << 4));
    const int pr = warp * 16 + g;
    const uint32_t qBase = smu + (uint32_t)(warp * 16 * 144) + offpat;
    const float LOG2E = 1.4426950408889634f;
    const float SCL   = 0.125f;   // 1/sqrt(64)

    for (int tile = blockIdx.x; tile < NT; tile += gridDim.x) {
        const int qt = tile & (SEQ / 128 - 1);          // 0..15
        const int h  = (tile >> 4) & (NHEAD - 1);       // 0..15
        const int b  = tile >> 8;                        // 0..1

        const size_t baseQK = ((size_t)(b * NHEAD + h)) * SEQ * HDIM;
        const __half* Qg = g_q + baseQK + (size_t)qt * 128 * HDIM;
        const __half* Kg = g_k + baseQK;
        const __half* Vg = g_v + ((size_t)(b * NHEAD + h)) * HDIM * SEQ;   // [d][s]

        #pragma unroll
        for (int i = 0; i < 4; i++) {
            int idx = tid + i * 256;
            int row = idx >> 3;
            int cp  = (idx & 7) << 3;
            CP_A16(smu + (uint32_t)(row * 144 + cp * 2), Qg + row * HDIM + cp);
        }
        CP_COMMIT();

        auto load_kv = [&](int st, int kt) {
            #pragma unroll
            for (int i = 0; i < 2; i++) {
                int idx = tid + i * 256;
                int row = idx >> 3;
                int cp  = (idx & 7) << 3;
                CP_A16(smu + (uint32_t)(QTB + st * STB + row * 144 + cp * 2),
                       Kg + ((size_t)kt * 64 + row) * HDIM + cp);
                CP_A16(smu + (uint32_t)(QTB + 2 * STB + st * STB + row * 144 + cp * 2),
                       Vg + (size_t)row * SEQ + kt * 64 + cp);
            }
            CP_COMMIT();
        };

        load_kv(0, 0);
        CP_WAIT1();       // Q group done (KV0 may still be in flight)
        __syncthreads();

        uint32_t qa[4][4];
        #pragma unroll
        for (int kk = 0; kk < 4; kk++)
            ldsm_x4(qa[kk][0], qa[kk][1], qa[kk][2], qa[kk][3], qBase + kk * 32);
        __syncthreads();   // everyone has Q frags before sQ is reused as P

        float oc[8][4] = {};
        float m0 = -1e30f, m1 = -1e30f, l0 = 0.0f, l1 = 0.0f;

        int st = 0;
        for (int kt = 0; kt < SEQ / 64; kt++, st ^= 1) {
            if (kt + 1 < SEQ / 64) { load_kv(st ^ 1, kt + 1); CP_WAIT1(); }
            else                   { CP_WAIT0(); }
            __syncthreads();

            const uint32_t kBase = smu + (uint32_t)(QTB + st * STB) + offpat;
            const uint32_t vBase = smu + (uint32_t)(QTB + 2 * STB + st * STB) + offpat;

            float sc[8][4] = {};
            #pragma unroll
            for (int kk = 0; kk < 4; kk++) {
                uint32_t bb[8][2];
                #pragma unroll
                for (int nb = 0; nb < 4; nb++)
                    ldsm_x4(bb[2 * nb][0], bb[2 * nb + 1][0], bb[2 * nb][1], bb[2 * nb + 1][1],
                            kBase + nb * 16 * 144 + kk * 32);
                #pragma unroll
                for (int ni = 0; ni < 8; ni++)
                    mma_f16(sc[ni], qa[kk], bb[ni]);
            }

            #pragma unroll
            for (int ni = 0; ni < 8; ni++)
                #pragma unroll
                for (int j = 0; j < 4; j++) sc[ni][j] *= SCL;

            float mx0 = -1e30f, mx1 = -1e30f;
            #pragma unroll
            for (int ni = 0; ni < 8; ni++) {
                mx0 = fmaxf(mx0, fmaxf(sc[ni][0], sc[ni][1]));
                mx1 = fmaxf(mx1, fmaxf(sc[ni][2], sc[ni][3]));
            }
            mx0 = fmaxf(mx0, __shfl_xor_sync(0xffffffffu, mx0, 1));
            mx0 = fmaxf(mx0, __shfl_xor_sync(0xffffffffu, mx0, 2));
            mx1 = fmaxf(mx1, __shfl_xor_sync(0xffffffffu, mx1, 1));
            mx1 = fmaxf(mx1, __shfl_xor_sync(0xffffffffu, mx1, 2));

            float mn0 = fmaxf(m0, mx0);
            float mn1 = fmaxf(m1, mx1);
            float a0 = ex2f((m0 - mn0) * LOG2E);
            float a1 = ex2f((m1 - mn1) * LOG2E);
            m0 = mn0; m1 = mn1;

            float rs0 = 0.0f, rs1 = 0.0f;
            #pragma unroll
            for (int ni = 0; ni < 8; ni++) {
                sc[ni][0] = ex2f((sc[ni][0] - m0) * LOG2E);
                sc[ni][1] = ex2f((sc[ni][1] - m0) * LOG2E);
                sc[ni][2] = ex2f((sc[ni][2] - m1) * LOG2E);
                sc[ni][3] = ex2f((sc[ni][3] - m1) * LOG2E);
                rs0 += sc[ni][0] + sc[ni][1];
                rs1 += sc[ni][2] + sc[ni][3];
            }
            rs0 += __shfl_xor_sync(0xffffffffu, rs0, 1);
            rs0 += __shfl_xor_sync(0xffffffffu, rs0, 2);
            rs1 += __shfl_xor_sync(0xffffffffu, rs1, 1);
            rs1 += __shfl_xor_sync(0xffffffffu, rs1, 2);
            l0 = l0 * a0 + rs0;
            l1 = l1 * a1 + rs1;

            #pragma unroll
            for (int ni = 0; ni < 8; ni++) {
                oc[ni][0] *= a0; oc[ni][1] *= a0;
                oc[ni][2] *= a1; oc[ni][3] *= a1;
            }

            #pragma unroll
            for (int ni = 0; ni < 8; ni++) {
                int cc = ni * 8 + 2 * t;
                *(__half2*)(sQh + pr * 72 + cc)       = __floats2half2_rn(sc[ni][0], sc[ni][1]);
                *(__half2*)(sQh + (pr + 8) * 72 + cc) = __floats2half2_rn(sc[ni][2], sc[ni][3]);
            }
            __syncwarp();

            #pragma unroll
            for (int kk = 0; kk < 4; kk++) {
                uint32_t pa[4];
                ldsm_x4(pa[0], pa[1], pa[2], pa[3], qBase + kk * 32);
                uint32_t bb[8][2];
                #pragma unroll
                for (int nb = 0; nb < 4; nb++)
                    ldsm_x4(bb[2 * nb][0], bb[2 * nb + 1][0], bb[2 * nb][1], bb[2 * nb + 1][1],
                            vBase + nb * 16 * 144 + kk * 32);
                #pragma unroll
                for (int ni = 0; ni < 8; ni++)
                    mma_f16(oc[ni], pa, bb[ni]);
            }
            __syncthreads();
        }

        float i0 = 1.0f / l0;
        float i1 = 1.0f / l1;
        int r0 = qt * 128 + warp * 16 + g;
        __half* Og = g_att + (size_t)b * SEQ * EDIM + (size_t)h * HDIM;
        #pragma unroll
        for (int ni = 0; ni < 8; ni++) {
            int cc = ni * 8 + 2 * t;
            *(__half2*)(Og + (size_t)r0 * EDIM + cc) =
                __floats2half2_rn(oc[ni][0] * i0, oc[ni][1] * i0);
            *(__half2*)(Og + (size_t)(r0 + 8) * EDIM + cc) =
                __floats2half2_rn(oc[ni][2] * i1, oc[ni][3] * i1);
        }
        __syncthreads();   // protect smem before next tile's Q/KV prologue
    }
}

extern "C" void kernel_launch(void* const* d_in, const int* in_sizes, int n_in,
                              void* d_out, int out_size)
{
    const float* x     = (const float*)d_in[0];
    const float* hmask = (const float*)d_in[1];
    const float* qkv_w = (const float*)d_in[2];
    const float* qkv_b = (const float*)d_in[3];
    const float* fc_w  = (const float*)d_in[4];
    const float* fc_b  = (const float*)d_in[5];
    float* out = (float*)d_out;

    const int gemm_smem = 3 * 2 * 128 * 144;                 // 110592 B
    const int fa_smem   = 128 * 144 + 4 * 64 * 144;          // 55296 B

    cudaFuncSetAttribute(gemm_f16_kernel<1>,
                         cudaFuncAttributeMaxDynamicSharedMemorySize, gemm_smem);
    cudaFuncSetAttribute(gemm_f16_kernel<0>,
                         cudaFuncAttributeMaxDynamicSharedMemorySize, gemm_smem);
    cudaFuncSetAttribute(flash_attn_kernel,
                         cudaFuncAttributeMaxDynamicSharedMemorySize, fa_smem);

    // 0) one fused fp32->fp16 conversion launch (x, qkv_w, fc_w)
    {
        int total4 = N4_X + N4_WQ + N4_WF;
        cvt_all_kernel<<<(total4 + 255) / 256, 256>>>(x, qkv_w, fc_w);
    }

    const int PERSIST = 296;   // 148 SMs x 2 CTAs

    // 1) QKV projection + bias + head_mask + scatter (persistent)
    {
        int NT  = (BATCH * SEQ / 128) * (3 * EDIM / 128);   // 32*24 = 768
        int NBX = 3 * EDIM / 128;                           // 24
        gemm_f16_kernel<1><<<PERSIST, 256, gemm_smem>>>(
            qkv_b, hmask, nullptr, BATCH * SEQ, 3 * EDIM, EDIM, NT, NBX);
    }

    // 2) flash attention -> g_att [B,S,D] (fp16, persistent)
    {
        int NT = (SEQ / 128) * NHEAD * BATCH;               // 512
        flash_attn_kernel<<<PERSIST, 256, fa_smem>>>(NT);
    }

    // 3) output projection + bias -> d_out (fp32, persistent; 256 tiles < 296)
    {
        int NT  = (BATCH * SEQ / 128) * (EDIM / 128);       // 32*8 = 256
        int NBX = EDIM / 128;                               // 8
        gemm_f16_kernel<0><<<NT, 256, gemm_smem>>>(
            fc_b, nullptr, out, BATCH * SEQ, EDIM, EDIM, NT, NBX);
    }
}